// round 4
// baseline (speedup 1.0000x reference)
#include <cuda_runtime.h>

// MMI softmax loss — collapsed form.
//
// reference:
//   examples  = emb[:2048]                      [2048, 32000]
//   negatives = emb[2048:10240]                 [8192, 32000]
//   contrast[d] = sum_{j=1..4} emb[d + j*2048]  (seg_ids = arange(8192) % 2048)
//   picked[d]  = examples[d, t_d] / contrast[d, t_d]
//   out        = -mean(picked)
//
// Only the t_d column of each row is ever observed, so we gather 5 scalars
// per d instead of touching the 1.3 GB plane: 10,240 scattered LDGs total.

#define DIM   2048
#define NCLS  32000LL
#define NBLK  32
#define TPB   64    // NBLK * TPB == DIM, one d per thread

__device__ float g_partial[NBLK];

__global__ void mmi_partial_kernel(const float* __restrict__ emb,
                                   const int* __restrict__ tgt) {
    const int d = blockIdx.x * TPB + threadIdx.x;   // 0..2047, exact cover

    const int t = __ldg(&tgt[d]);
    const float* col = emb + (long long)t;          // column base

    // 5 independent gathers (MLP=5 per thread; PTW overlapped)
    const float ex = __ldg(col + (long long)d * NCLS);
    const float c0 = __ldg(col + (long long)(d + 1 * DIM) * NCLS);
    const float c1 = __ldg(col + (long long)(d + 2 * DIM) * NCLS);
    const float c2 = __ldg(col + (long long)(d + 3 * DIM) * NCLS);
    const float c3 = __ldg(col + (long long)(d + 4 * DIM) * NCLS);

    float v = ex / (((c0 + c1) + c2) + c3);

    // warp reduce
    #pragma unroll
    for (int o = 16; o; o >>= 1)
        v += __shfl_xor_sync(0xffffffffu, v, o);

    __shared__ float s[TPB / 32];
    if ((threadIdx.x & 31) == 0) s[threadIdx.x >> 5] = v;
    __syncthreads();

    if (threadIdx.x == 0)
        g_partial[blockIdx.x] = s[0] + s[1];
}

__global__ void mmi_final_kernel(float* __restrict__ out) {
    // NBLK == 32: one warp folds all partials
    float v = g_partial[threadIdx.x];
    #pragma unroll
    for (int o = 16; o; o >>= 1)
        v += __shfl_xor_sync(0xffffffffu, v, o);
    if (threadIdx.x == 0)
        *out = -(v / (float)DIM);
}

extern "C" void kernel_launch(void* const* d_in, const int* in_sizes, int n_in,
                              void* d_out, int out_size) {
    const float* emb = (const float*)d_in[0];   // embeddings [10240, 32000] f32
    const int*   tgt = (const int*)d_in[1];     // targets [2048] i32

    mmi_partial_kernel<<<NBLK, TPB>>>(emb, tgt);
    mmi_final_kernel<<<1, 32>>>((float*)d_out);
}